// round 2
// baseline (speedup 1.0000x reference)
#include <cuda_runtime.h>
#include <cstdint>

#define TT    1024
#define BB    4
#define EE    1024
#define HH    16
#define ML    1024
#define MROWS (TT*BB)      // 4096
#define QKVN  (3*EE)       // 3072

// Scratch (device globals: allocation-free per harness rules)
__device__ float g_qkv[MROWS * QKVN];   // (t*B+b, 3E)
__device__ float g_ctx[MROWS];          // ctx at index t*B+b
__device__ float g_attn[MROWS * EE];    // attention output (T,B,E)

struct __align__(16) u64x2 { unsigned long long a, b; };

// ---------- f32x2 helpers (B300 packed fp32: 2x FFMA throughput, PTX-only) ----------
__device__ __forceinline__ unsigned long long splat2(float x) {
    unsigned long long r; asm("mov.b64 %0, {%1, %1};" : "=l"(r) : "f"(x)); return r;
}
__device__ __forceinline__ void ffma2(unsigned long long& d, unsigned long long a, unsigned long long b) {
    asm("fma.rn.f32x2 %0, %1, %2, %0;" : "+l"(d) : "l"(a), "l"(b));
}
__device__ __forceinline__ void fmul2(unsigned long long& d, unsigned long long a) {
    asm("mul.rn.f32x2 %0, %0, %1;" : "+l"(d) : "l"(a));
}
__device__ __forceinline__ float2 unpk(unsigned long long p) {
    float2 f; asm("mov.b64 {%0, %1}, %2;" : "=f"(f.x), "=f"(f.y) : "l"(p)); return f;
}
__device__ __forceinline__ float redmax16(float v) {
    #pragma unroll
    for (int o = 8; o; o >>= 1) v = fmaxf(v, __shfl_xor_sync(0xffffffffu, v, o));
    return v;
}
__device__ __forceinline__ float redsum16(float v) {
    #pragma unroll
    for (int o = 8; o; o >>= 1) v += __shfl_xor_sync(0xffffffffu, v, o);
    return v;
}
// log(sigmoid(x)) = min(x,0) - log(1+exp(-|x|))
__device__ __forceinline__ float logsig(float x) {
    return fminf(x, 0.0f) - __logf(1.0f + __expf(-fabsf(x)));
}

// ---------------- SGEMM (NT): C[m][n] = bias[n] + sum_k A[m][k]*W[n][k] ----------------
// 128x128 tile, BK=16, 256 threads, 8x8 per thread (4+4 split), f32x2 accumulators.
__global__ __launch_bounds__(256) void sgemm_nt(
    const float* __restrict__ A, const float* __restrict__ W,
    const float* __restrict__ bias, float* __restrict__ C,
    int M, int N, int K)
{
    __shared__ float As[16][132];   // [k][m]
    __shared__ float Bs[16][132];   // [k][n]

    const int tid = threadIdx.x;
    const int tx = tid & 15, ty = tid >> 4;
    const int n0 = blockIdx.x * 128, m0 = blockIdx.y * 128;

    unsigned long long acc[8][4];
    #pragma unroll
    for (int i = 0; i < 8; i++)
        #pragma unroll
        for (int j = 0; j < 4; j++) acc[i][j] = 0ull;

    const int r0 = tid >> 2;          // 0..63
    const int c0 = (tid & 3) * 4;     // 0,4,8,12
    const float* Ag = A + (size_t)(m0 + r0) * K + c0;
    const float* Wg = W + (size_t)(n0 + r0) * K + c0;

    float4 a0 = *(const float4*)Ag;
    float4 a1 = *(const float4*)(Ag + (size_t)64 * K);
    float4 b0 = *(const float4*)Wg;
    float4 b1 = *(const float4*)(Wg + (size_t)64 * K);

    for (int kt = 0; kt < K; kt += 16) {
        __syncthreads();
        As[c0+0][r0] = a0.x; As[c0+1][r0] = a0.y; As[c0+2][r0] = a0.z; As[c0+3][r0] = a0.w;
        As[c0+0][r0+64] = a1.x; As[c0+1][r0+64] = a1.y; As[c0+2][r0+64] = a1.z; As[c0+3][r0+64] = a1.w;
        Bs[c0+0][r0] = b0.x; Bs[c0+1][r0] = b0.y; Bs[c0+2][r0] = b0.z; Bs[c0+3][r0] = b0.w;
        Bs[c0+0][r0+64] = b1.x; Bs[c0+1][r0+64] = b1.y; Bs[c0+2][r0+64] = b1.z; Bs[c0+3][r0+64] = b1.w;
        __syncthreads();

        if (kt + 16 < K) {
            a0 = *(const float4*)(Ag + kt + 16);
            a1 = *(const float4*)(Ag + (size_t)64 * K + kt + 16);
            b0 = *(const float4*)(Wg + kt + 16);
            b1 = *(const float4*)(Wg + (size_t)64 * K + kt + 16);
        }

        #pragma unroll
        for (int k = 0; k < 16; k++) {
            float4 aL = *(const float4*)&As[k][ty * 4];
            float4 aH = *(const float4*)&As[k][ty * 4 + 64];
            u64x2 bL = *(const u64x2*)&Bs[k][tx * 4];
            u64x2 bH = *(const u64x2*)&Bs[k][tx * 4 + 64];
            float am[8] = {aL.x, aL.y, aL.z, aL.w, aH.x, aH.y, aH.z, aH.w};
            #pragma unroll
            for (int j = 0; j < 8; j++) {
                unsigned long long s = splat2(am[j]);
                ffma2(acc[j][0], s, bL.a); ffma2(acc[j][1], s, bL.b);
                ffma2(acc[j][2], s, bH.a); ffma2(acc[j][3], s, bH.b);
            }
        }
    }

    float bnL[4], bnH[4];
    #pragma unroll
    for (int j = 0; j < 4; j++) {
        bnL[j] = __ldg(bias + n0 + tx * 4 + j);
        bnH[j] = __ldg(bias + n0 + 64 + tx * 4 + j);
    }
    #pragma unroll
    for (int jm = 0; jm < 8; jm++) {
        int m = m0 + ((jm < 4) ? (ty * 4 + jm) : (64 + ty * 4 + jm - 4));
        float* Cp = C + (size_t)m * N + n0;
        float2 p0 = unpk(acc[jm][0]), p1 = unpk(acc[jm][1]);
        float2 p2 = unpk(acc[jm][2]), p3 = unpk(acc[jm][3]);
        *(float4*)(Cp + tx * 4)      = make_float4(p0.x + bnL[0], p0.y + bnL[1], p1.x + bnL[2], p1.y + bnL[3]);
        *(float4*)(Cp + 64 + tx * 4) = make_float4(p2.x + bnH[0], p2.y + bnH[1], p3.x + bnH[2], p3.y + bnH[3]);
    }
}

// ---------------- ctx GEMV: ctx[t*B+b] = query_row . ctx_w ----------------
__global__ __launch_bounds__(256) void ctx_kernel(
    const float* __restrict__ q, const float* __restrict__ w, float* __restrict__ out)
{
    int row = blockIdx.x * 8 + (threadIdx.x >> 5);
    int lane = threadIdx.x & 31;
    const float* qr = q + (size_t)row * EE;
    float s = 0.f;
    #pragma unroll
    for (int i = 0; i < EE; i += 128) {
        float4 qa = *(const float4*)(qr + i + lane * 4);
        float4 wa = *(const float4*)(w + i + lane * 4);
        s += qa.x * wa.x + qa.y * wa.y + qa.z * wa.z + qa.w * wa.w;
    }
    #pragma unroll
    for (int o = 16; o; o >>= 1) s += __shfl_xor_sync(0xffffffffu, s, o);
    if (!lane) out[row] = s;
}

// ---------------- Fused flash attention with logsigmoid bias ----------------
// grid (16 q-tiles, 64 batch-heads), 256 threads (tx 0..15, ty 0..15).
// Thread: rows i = ty*4+ji; S cols s = {2tx,2tx+1,2tx+32,2tx+33}; O cols d = tx*4..tx*4+3.
// Ks is k-major [k][64] with XOR-(2*(k>>2)) column swizzle -> conflict-free
// transpose stores AND conflict-free paired reads.
__global__ __launch_bounds__(256, 2) void attn_kernel(
    const float* __restrict__ fwd, const float* __restrict__ bwd,
    const float* __restrict__ head_x)
{
    extern __shared__ float sm[];
    float* Qs  = sm;              // [64][64] row-major (i,k)
    float* Ks  = sm + 4096;       // [64 k][64] swizzled columns
    float* Vs  = sm + 8192;       // [64 s][64 d]
    float* Ps  = sm + 12288;      // [64 i][68]
    float* pos = sm + 16640;      // [2049]

    const int tid = threadIdx.x;
    const int tx = tid & 15, ty = tid >> 4;
    const int t0 = blockIdx.x * 64;
    const int bh = blockIdx.y;
    const int b = bh >> 4, h = bh & 15;

    for (int j = tid; j < 2049; j += 256)
        pos[j] = (j < 1024) ? fwd[j] : ((j == 1024) ? 0.f : bwd[j - 1025]);

    #pragma unroll
    for (int s4 = 0; s4 < 4; s4++) {
        int idx = tid + 256 * s4;
        int r = idx >> 4, g = idx & 15;
        float4 v = *(const float4*)(g_qkv + ((size_t)(t0 + r) * BB + b) * QKVN + h * 64 + g * 4);
        *(float4*)&Qs[r * 64 + g * 4] = v;
    }

    const float hx = __ldg(head_x + h);
    float cv[4], mrow[4], lrow[4];
    unsigned long long O[4][2];
    #pragma unroll
    for (int ji = 0; ji < 4; ji++) {
        cv[ji] = g_ctx[(size_t)(t0 + ty * 4 + ji) * BB + b];
        mrow[ji] = -1e30f; lrow[ji] = 0.f;
        O[ji][0] = 0ull; O[ji][1] = 0ull;
    }

    for (int it = 0; it < 16; it++) {
        const int s0 = it * 64;

        float4 kreg[4], vreg[4];
        #pragma unroll
        for (int s4 = 0; s4 < 4; s4++) {
            int idx = tid + 256 * s4;
            int r = idx >> 4, g = idx & 15;
            size_t base = ((size_t)(s0 + r) * BB + b) * QKVN + h * 64 + g * 4;
            kreg[s4] = *(const float4*)(g_qkv + base + EE);
            vreg[s4] = *(const float4*)(g_qkv + base + 2 * EE);
        }
        __syncthreads();   // prior iter done reading Ks/Vs (also covers Qs/pos first time)
        #pragma unroll
        for (int s4 = 0; s4 < 4; s4++) {
            int idx = tid + 256 * s4;
            int r = idx >> 4, g = idx & 15;
            int cb = r ^ (2 * g);  // swizzled column
            Ks[(g * 4 + 0) * 64 + cb] = kreg[s4].x;
            Ks[(g * 4 + 1) * 64 + cb] = kreg[s4].y;
            Ks[(g * 4 + 2) * 64 + cb] = kreg[s4].z;
            Ks[(g * 4 + 3) * 64 + cb] = kreg[s4].w;
            *(float4*)&Vs[r * 64 + g * 4] = vreg[s4];
        }
        __syncthreads();   // K/V ready

        // ---- S = Q K^T (f32x2, pairs along s) ----
        unsigned long long S[4][2];
        #pragma unroll
        for (int ji = 0; ji < 4; ji++) { S[ji][0] = 0ull; S[ji][1] = 0ull; }
        #pragma unroll
        for (int k4 = 0; k4 < 16; k4++) {
            int co = (2 * tx) ^ (2 * k4);  // swizzled read column for pair base
            float4 qv[4];
            #pragma unroll
            for (int ji = 0; ji < 4; ji++)
                qv[ji] = *(const float4*)&Qs[(ty * 4 + ji) * 64 + k4 * 4];
            #pragma unroll
            for (int kk = 0; kk < 4; kk++) {
                int k = k4 * 4 + kk;
                unsigned long long k0 = *(const unsigned long long*)&Ks[k * 64 + co];
                unsigned long long k1 = *(const unsigned long long*)&Ks[k * 64 + co + 32];
                #pragma unroll
                for (int ji = 0; ji < 4; ji++) {
                    float qs = (kk == 0) ? qv[ji].x : (kk == 1) ? qv[ji].y
                             : (kk == 2) ? qv[ji].z : qv[ji].w;
                    unsigned long long a = splat2(qs);
                    ffma2(S[ji][0], a, k0);
                    ffma2(S[ji][1], a, k1);
                }
            }
        }

        // ---- bias + online softmax ----
        #pragma unroll
        for (int ji = 0; ji < 4; ji++) {
            float2 sa = unpk(S[ji][0]);
            float2 sb = unpk(S[ji][1]);
            int row = ty * 4 + ji;
            int dbase = s0 + 2 * tx - (t0 + row) + ML;
            float cb = cv[ji] + hx;
            float v0 = sa.x + logsig(cb + pos[dbase]);
            float v1 = sa.y + logsig(cb + pos[dbase + 1]);
            float v2 = sb.x + logsig(cb + pos[dbase + 32]);
            float v3 = sb.y + logsig(cb + pos[dbase + 33]);
            float tmx = redmax16(fmaxf(fmaxf(v0, v1), fmaxf(v2, v3)));
            float mnew = fmaxf(mrow[ji], tmx);
            float sc = __expf(mrow[ji] - mnew);
            mrow[ji] = mnew;
            float p0 = __expf(v0 - mnew), p1 = __expf(v1 - mnew);
            float p2 = __expf(v2 - mnew), p3 = __expf(v3 - mnew);
            lrow[ji] = lrow[ji] * sc + redsum16(p0 + p1 + p2 + p3);
            unsigned long long scp = splat2(sc);
            fmul2(O[ji][0], scp); fmul2(O[ji][1], scp);
            *(float2*)&Ps[row * 68 + 2 * tx]      = make_float2(p0, p1);
            *(float2*)&Ps[row * 68 + 2 * tx + 32] = make_float2(p2, p3);
        }
        __syncthreads();   // Ps ready

        // ---- O += P V ----
        #pragma unroll
        for (int s4 = 0; s4 < 16; s4++) {
            float4 pv[4];
            #pragma unroll
            for (int ji = 0; ji < 4; ji++)
                pv[ji] = *(const float4*)&Ps[(ty * 4 + ji) * 68 + s4 * 4];
            #pragma unroll
            for (int ss = 0; ss < 4; ss++) {
                int s = s4 * 4 + ss;
                u64x2 vvp = *(const u64x2*)&Vs[s * 64 + tx * 4];
                #pragma unroll
                for (int ji = 0; ji < 4; ji++) {
                    float p = (ss == 0) ? pv[ji].x : (ss == 1) ? pv[ji].y
                            : (ss == 2) ? pv[ji].z : pv[ji].w;
                    unsigned long long sp = splat2(p);
                    ffma2(O[ji][0], sp, vvp.a);
                    ffma2(O[ji][1], sp, vvp.b);
                }
            }
        }
    }

    // ---- finalize: O / l, write (T,B,E) layout ----
    #pragma unroll
    for (int ji = 0; ji < 4; ji++) {
        float rl = 1.0f / lrow[ji];
        float2 o0 = unpk(O[ji][0]), o1 = unpk(O[ji][1]);
        int row = t0 + ty * 4 + ji;
        float* dst = g_attn + ((size_t)row * BB + b) * EE + h * 64 + tx * 4;
        *(float4*)dst = make_float4(o0.x * rl, o0.y * rl, o1.x * rl, o1.y * rl);
    }
}

extern "C" void kernel_launch(void* const* d_in, const int* in_sizes, int n_in,
                              void* d_out, int out_size) {
    const float* query = (const float*)d_in[0];
    const float* ipw   = (const float*)d_in[1];
    const float* ipb   = (const float*)d_in[2];
    const float* fwd   = (const float*)d_in[3];
    const float* bwd   = (const float*)d_in[4];
    const float* hx    = (const float*)d_in[5];
    const float* cw    = (const float*)d_in[6];
    const float* ow    = (const float*)d_in[7];
    const float* ob    = (const float*)d_in[8];
    float* out = (float*)d_out;

    float *qkv_p, *ctx_p, *attn_p;
    cudaGetSymbolAddress((void**)&qkv_p,  g_qkv);
    cudaGetSymbolAddress((void**)&ctx_p,  g_ctx);
    cudaGetSymbolAddress((void**)&attn_p, g_attn);

    // QKV projection: (4096,1024) x (3072,1024)^T
    sgemm_nt<<<dim3(QKVN / 128, MROWS / 128), 256>>>(query, ipw, ipb, qkv_p, MROWS, QKVN, EE);

    // context gate GEMV
    ctx_kernel<<<MROWS / 8, 256>>>(query, cw, ctx_p);

    // fused flash attention
    const int smem = (4096 * 3 + 64 * 68 + 2049) * 4;  // 74756 B
    cudaFuncSetAttribute(attn_kernel, cudaFuncAttributeMaxDynamicSharedMemorySize, smem);
    attn_kernel<<<dim3(TT / 64, BB * HH), 256, smem>>>(fwd, bwd, hx);

    // output projection: (4096,1024) x (1024,1024)^T
    sgemm_nt<<<dim3(EE / 128, MROWS / 128), 256>>>(attn_p, ow, ob, out, MROWS, EE, EE);
}

// round 4
// speedup vs baseline: 1.6009x; 1.6009x over previous
#include <cuda_runtime.h>
#include <cuda_bf16.h>
#include <cstdint>

#define TT    1024
#define BB    4
#define EE    1024
#define HH    16
#define ML    1024
#define MROWS (TT*BB)      // 4096
#define QKVN  (3*EE)       // 3072

// ---------------- scratch (device globals; allocation-free) ----------------
__device__ float g_qkv[MROWS * QKVN];
__device__ float g_ctx[MROWS];
__device__ float g_attn[MROWS * EE];
__device__ __nv_bfloat16 g_qh[MROWS * EE],  g_ql[MROWS * EE];
__device__ __nv_bfloat16 g_wh[QKVN * EE],   g_wl[QKVN * EE];
__device__ __nv_bfloat16 g_ah[MROWS * EE],  g_al[MROWS * EE];
__device__ __nv_bfloat16 g_oh[EE * EE],     g_ol[EE * EE];

struct __align__(16) u64x2 { unsigned long long a, b; };

// ---------------- PTX helpers (all base-sm_103-safe) ----------------
__device__ __forceinline__ uint32_t smem_u32(const void* p) {
    uint32_t a;
    asm("{ .reg .u64 t; cvta.to.shared.u64 t, %1; cvt.u32.u64 %0, t; }" : "=r"(a) : "l"(p));
    return a;
}
__device__ __forceinline__ void cp_async16(uint32_t s, const void* g) {
    asm volatile("cp.async.cg.shared.global [%0], [%1], 16;" :: "r"(s), "l"(g));
}
__device__ __forceinline__ void cp_commit() { asm volatile("cp.async.commit_group;" ::: "memory"); }
template <int N> __device__ __forceinline__ void cp_wait() {
    asm volatile("cp.async.wait_group %0;" :: "n"(N) : "memory");
}
__device__ __forceinline__ void ldm_x4(uint32_t* r, uint32_t addr) {
    asm volatile("ldmatrix.sync.aligned.m8n8.x4.shared.b16 {%0,%1,%2,%3}, [%4];"
                 : "=r"(r[0]), "=r"(r[1]), "=r"(r[2]), "=r"(r[3]) : "r"(addr));
}
__device__ __forceinline__ void mma_bf16(float* d, const uint32_t* a, const uint32_t* b) {
    asm volatile("mma.sync.aligned.m16n8k16.row.col.f32.bf16.bf16.f32 "
                 "{%0,%1,%2,%3}, {%4,%5,%6,%7}, {%8,%9}, {%0,%1,%2,%3};"
                 : "+f"(d[0]), "+f"(d[1]), "+f"(d[2]), "+f"(d[3])
                 : "r"(a[0]), "r"(a[1]), "r"(a[2]), "r"(a[3]), "r"(b[0]), "r"(b[1]));
}

// f32x2 helpers (attention kernel)
__device__ __forceinline__ unsigned long long splat2(float x) {
    unsigned long long r; asm("mov.b64 %0, {%1, %1};" : "=l"(r) : "f"(x)); return r;
}
__device__ __forceinline__ void ffma2(unsigned long long& d, unsigned long long a, unsigned long long b) {
    asm("fma.rn.f32x2 %0, %1, %2, %0;" : "+l"(d) : "l"(a), "l"(b));
}
__device__ __forceinline__ void fmul2(unsigned long long& d, unsigned long long a) {
    asm("mul.rn.f32x2 %0, %0, %1;" : "+l"(d) : "l"(a));
}
__device__ __forceinline__ float2 unpk(unsigned long long p) {
    float2 f; asm("mov.b64 {%0, %1}, %2;" : "=f"(f.x), "=f"(f.y) : "l"(p)); return f;
}
__device__ __forceinline__ float redmax16(float v) {
    #pragma unroll
    for (int o = 8; o; o >>= 1) v = fmaxf(v, __shfl_xor_sync(0xffffffffu, v, o));
    return v;
}
__device__ __forceinline__ float redsum16(float v) {
    #pragma unroll
    for (int o = 8; o; o >>= 1) v += __shfl_xor_sync(0xffffffffu, v, o);
    return v;
}
__device__ __forceinline__ float logsig(float x) {
    return fminf(x, 0.0f) - __logf(1.0f + __expf(-fabsf(x)));
}

// ---------------- fp32 -> bf16 hi/lo split ----------------
__global__ __launch_bounds__(256) void cvt_split(
    const float4* __restrict__ x, __nv_bfloat162* __restrict__ hi,
    __nv_bfloat162* __restrict__ lo, int n4)
{
    int i = blockIdx.x * 256 + threadIdx.x;
    if (i >= n4) return;
    float4 v = x[i];
    __nv_bfloat16 h0 = __float2bfloat16_rn(v.x);
    __nv_bfloat16 h1 = __float2bfloat16_rn(v.y);
    __nv_bfloat16 h2 = __float2bfloat16_rn(v.z);
    __nv_bfloat16 h3 = __float2bfloat16_rn(v.w);
    __nv_bfloat16 l0 = __float2bfloat16_rn(v.x - __bfloat162float(h0));
    __nv_bfloat16 l1 = __float2bfloat16_rn(v.y - __bfloat162float(h1));
    __nv_bfloat16 l2 = __float2bfloat16_rn(v.z - __bfloat162float(h2));
    __nv_bfloat16 l3 = __float2bfloat16_rn(v.w - __bfloat162float(h3));
    hi[2*i]   = __nv_bfloat162(h0, h1);
    hi[2*i+1] = __nv_bfloat162(h2, h3);
    lo[2*i]   = __nv_bfloat162(l0, l1);
    lo[2*i+1] = __nv_bfloat162(l2, l3);
}

// ---------------- split-bf16 HMMA GEMM (NT): C = bias + A W^T ----------------
// 128x128 CTA tile, BK=64, 8 warps (warp tile 32x64), double-buffered cp.async.
// D = Ah*Bh + Ah*Bl + Al*Bh, fp32 accumulate.
__global__ __launch_bounds__(256) void hmma_gemm(
    const __nv_bfloat16* __restrict__ Ah, const __nv_bfloat16* __restrict__ Al,
    const __nv_bfloat16* __restrict__ Bh, const __nv_bfloat16* __restrict__ Bl,
    const float* __restrict__ bias, float* __restrict__ C, int N, int K)
{
    extern __shared__ char dsm[];   // 2 stages x 64KB: [Ah|Al|Bh|Bl] 16KB each
    const int tid = threadIdx.x;
    const int wid = tid >> 5, lane = tid & 31;
    const int n0 = blockIdx.x * 128, m0 = blockIdx.y * 128;
    const uint32_t sbase = smem_u32(dsm);

    const int mb = (wid >> 1) * 32;    // warp m offset (0,32,64,96)
    const int nb = (wid & 1) * 64;     // warp n offset (0,64)

    float acc[16][4];
    #pragma unroll
    for (int i = 0; i < 16; i++)
        #pragma unroll
        for (int j = 0; j < 4; j++) acc[i][j] = 0.f;

    const int nkt = K >> 6;

    auto load_tile = [&](int kt, int stage) {
        uint32_t sb = sbase + stage * 65536;
        const int koff = kt * 64;
        #pragma unroll
        for (int i = 0; i < 16; i++) {
            int c = tid + 256 * i;
            int sub = c >> 10;              // 0 Ah, 1 Al, 2 Bh, 3 Bl
            int idx = c & 1023;
            int row = idx >> 3, ch = idx & 7;
            const __nv_bfloat16* src =
                (sub == 0) ? Ah + (size_t)(m0 + row) * K :
                (sub == 1) ? Al + (size_t)(m0 + row) * K :
                (sub == 2) ? Bh + (size_t)(n0 + row) * K :
                             Bl + (size_t)(n0 + row) * K;
            uint32_t saddr = sb + sub * 16384 + row * 128 + ((ch ^ (row & 7)) << 4);
            cp_async16(saddr, src + koff + ch * 8);
        }
        cp_commit();
    };

    // per-lane ldmatrix source coords
    const int arow = lane & 15, ach = lane >> 4;                       // A: +row, +chunk
    const int brow = (lane & 7) + ((lane >> 4) << 3), bch = (lane >> 3) & 1;

    load_tile(0, 0);
    for (int kt = 0; kt < nkt; kt++) {
        const int s = kt & 1;
        cp_wait<0>();
        __syncthreads();
        if (kt + 1 < nkt) load_tile(kt + 1, s ^ 1);

        uint32_t sb = sbase + s * 65536;
        #pragma unroll
        for (int kc = 0; kc < 4; kc++) {
            uint32_t fa[2][2][4];   // [h/l][mt][4]
            uint32_t fb[2][4][4];   // [h/l][bt][4]
            #pragma unroll
            for (int mt = 0; mt < 2; mt++) {
                int row = mb + mt * 16 + arow;
                int ch = kc * 2 + ach;
                uint32_t off = row * 128 + ((ch ^ (row & 7)) << 4);
                ldm_x4(fa[0][mt], sb + off);            // Ah
                ldm_x4(fa[1][mt], sb + 16384 + off);    // Al
            }
            #pragma unroll
            for (int bt = 0; bt < 4; bt++) {
                int row = nb + bt * 16 + brow;
                int ch = kc * 2 + bch;
                uint32_t off = row * 128 + ((ch ^ (row & 7)) << 4);
                ldm_x4(fb[0][bt], sb + 32768 + off);    // Bh
                ldm_x4(fb[1][bt], sb + 49152 + off);    // Bl
            }
            #pragma unroll
            for (int mt = 0; mt < 2; mt++)
                #pragma unroll
                for (int nt = 0; nt < 8; nt++) {
                    const uint32_t* bh = &fb[0][nt >> 1][(nt & 1) * 2];
                    const uint32_t* bl = &fb[1][nt >> 1][(nt & 1) * 2];
                    float* d = acc[mt * 8 + nt];
                    mma_bf16(d, fa[0][mt], bh);   // Ah*Bh
                    mma_bf16(d, fa[0][mt], bl);   // Ah*Bl
                    mma_bf16(d, fa[1][mt], bh);   // Al*Bh
                }
        }
        __syncthreads();
    }

    // epilogue: direct float2 stores + bias
    const int lr = lane >> 2, lc = (lane & 3) * 2;
    #pragma unroll
    for (int mt = 0; mt < 2; mt++)
        #pragma unroll
        for (int nt = 0; nt < 8; nt++) {
            int n = n0 + nb + nt * 8 + lc;
            float2 bv = *(const float2*)(bias + n);
            float* d = acc[mt * 8 + nt];
            int r0 = m0 + mb + mt * 16 + lr;
            *(float2*)(C + (size_t)r0 * N + n) = make_float2(d[0] + bv.x, d[1] + bv.y);
            *(float2*)(C + (size_t)(r0 + 8) * N + n) = make_float2(d[2] + bv.x, d[3] + bv.y);
        }
}

// ---------------- ctx GEMV ----------------
__global__ __launch_bounds__(256) void ctx_kernel(
    const float* __restrict__ q, const float* __restrict__ w, float* __restrict__ out)
{
    int row = blockIdx.x * 8 + (threadIdx.x >> 5);
    int lane = threadIdx.x & 31;
    const float* qr = q + (size_t)row * EE;
    float s = 0.f;
    #pragma unroll
    for (int i = 0; i < EE; i += 128) {
        float4 qa = *(const float4*)(qr + i + lane * 4);
        float4 wa = *(const float4*)(w + i + lane * 4);
        s += qa.x * wa.x + qa.y * wa.y + qa.z * wa.z + qa.w * wa.w;
    }
    #pragma unroll
    for (int o = 16; o; o >>= 1) s += __shfl_xor_sync(0xffffffffu, s, o);
    if (!lane) out[row] = s;
}

// ---------------- Fused flash attention with logsigmoid bias ----------------
__global__ __launch_bounds__(256, 2) void attn_kernel(
    const float* __restrict__ fwd, const float* __restrict__ bwd,
    const float* __restrict__ head_x)
{
    extern __shared__ float sm[];
    float* Qs  = sm;
    float* Ks  = sm + 4096;
    float* Vs  = sm + 8192;
    float* Ps  = sm + 12288;
    float* pos = sm + 16640;

    const int tid = threadIdx.x;
    const int tx = tid & 15, ty = tid >> 4;
    const int t0 = blockIdx.x * 64;
    const int bh = blockIdx.y;
    const int b = bh >> 4, h = bh & 15;

    for (int j = tid; j < 2049; j += 256)
        pos[j] = (j < 1024) ? fwd[j] : ((j == 1024) ? 0.f : bwd[j - 1025]);

    #pragma unroll
    for (int s4 = 0; s4 < 4; s4++) {
        int idx = tid + 256 * s4;
        int r = idx >> 4, g = idx & 15;
        float4 v = *(const float4*)(g_qkv + ((size_t)(t0 + r) * BB + b) * QKVN + h * 64 + g * 4);
        *(float4*)&Qs[r * 64 + g * 4] = v;
    }

    const float hx = __ldg(head_x + h);
    float cv[4], mrow[4], lrow[4];
    unsigned long long O[4][2];
    #pragma unroll
    for (int ji = 0; ji < 4; ji++) {
        cv[ji] = g_ctx[(size_t)(t0 + ty * 4 + ji) * BB + b];
        mrow[ji] = -1e30f; lrow[ji] = 0.f;
        O[ji][0] = 0ull; O[ji][1] = 0ull;
    }

    for (int it = 0; it < 16; it++) {
        const int s0 = it * 64;
        float4 kreg[4], vreg[4];
        #pragma unroll
        for (int s4 = 0; s4 < 4; s4++) {
            int idx = tid + 256 * s4;
            int r = idx >> 4, g = idx & 15;
            size_t bse = ((size_t)(s0 + r) * BB + b) * QKVN + h * 64 + g * 4;
            kreg[s4] = *(const float4*)(g_qkv + bse + EE);
            vreg[s4] = *(const float4*)(g_qkv + bse + 2 * EE);
        }
        __syncthreads();
        #pragma unroll
        for (int s4 = 0; s4 < 4; s4++) {
            int idx = tid + 256 * s4;
            int r = idx >> 4, g = idx & 15;
            int cb = r ^ (2 * g);
            Ks[(g * 4 + 0) * 64 + cb] = kreg[s4].x;
            Ks[(g * 4 + 1) * 64 + cb] = kreg[s4].y;
            Ks[(g * 4 + 2) * 64 + cb] = kreg[s4].z;
            Ks[(g * 4 + 3) * 64 + cb] = kreg[s4].w;
            *(float4*)&Vs[r * 64 + g * 4] = vreg[s4];
        }
        __syncthreads();

        unsigned long long S[4][2];
        #pragma unroll
        for (int ji = 0; ji < 4; ji++) { S[ji][0] = 0ull; S[ji][1] = 0ull; }
        #pragma unroll
        for (int k4 = 0; k4 < 16; k4++) {
            int co = (2 * tx) ^ (2 * k4);
            float4 qv[4];
            #pragma unroll
            for (int ji = 0; ji < 4; ji++)
                qv[ji] = *(const float4*)&Qs[(ty * 4 + ji) * 64 + k4 * 4];
            #pragma unroll
            for (int kk = 0; kk < 4; kk++) {
                int k = k4 * 4 + kk;
                unsigned long long k0 = *(const unsigned long long*)&Ks[k * 64 + co];
                unsigned long long k1 = *(const unsigned long long*)&Ks[k * 64 + co + 32];
                #pragma unroll
                for (int ji = 0; ji < 4; ji++) {
                    float qs = (kk == 0) ? qv[ji].x : (kk == 1) ? qv[ji].y
                             : (kk == 2) ? qv[ji].z : qv[ji].w;
                    unsigned long long a = splat2(qs);
                    ffma2(S[ji][0], a, k0);
                    ffma2(S[ji][1], a, k1);
                }
            }
        }

        #pragma unroll
        for (int ji = 0; ji < 4; ji++) {
            float2 sa = unpk(S[ji][0]);
            float2 sb = unpk(S[ji][1]);
            int row = ty * 4 + ji;
            int dbase = s0 + 2 * tx - (t0 + row) + ML;
            float cb = cv[ji] + hx;
            float v0 = sa.x + logsig(cb + pos[dbase]);
            float v1 = sa.y + logsig(cb + pos[dbase + 1]);
            float v2 = sb.x + logsig(cb + pos[dbase + 32]);
            float v3 = sb.y + logsig(cb + pos[dbase + 33]);
            float tmx = redmax16(fmaxf(fmaxf(v0, v1), fmaxf(v2, v3)));
            float mnew = fmaxf(mrow[ji], tmx);
            float sc = __expf(mrow[ji] - mnew);
            mrow[ji] = mnew;
            float p0 = __expf(v0 - mnew), p1 = __expf(v1 - mnew);
            float p2 = __expf(v2 - mnew), p3 = __expf(v3 - mnew);
            lrow[ji] = lrow[ji] * sc + redsum16(p0 + p1 + p2 + p3);
            unsigned long long scp = splat2(sc);
            fmul2(O[ji][0], scp); fmul2(O[ji][1], scp);
            *(float2*)&Ps[row * 68 + 2 * tx]      = make_float2(p0, p1);
            *(float2*)&Ps[row * 68 + 2 * tx + 32] = make_float2(p2, p3);
        }
        __syncthreads();

        #pragma unroll
        for (int s4 = 0; s4 < 16; s4++) {
            float4 pv[4];
            #pragma unroll
            for (int ji = 0; ji < 4; ji++)
                pv[ji] = *(const float4*)&Ps[(ty * 4 + ji) * 68 + s4 * 4];
            #pragma unroll
            for (int ss = 0; ss < 4; ss++) {
                int s = s4 * 4 + ss;
                u64x2 vvp = *(const u64x2*)&Vs[s * 64 + tx * 4];
                #pragma unroll
                for (int ji = 0; ji < 4; ji++) {
                    float p = (ss == 0) ? pv[ji].x : (ss == 1) ? pv[ji].y
                            : (ss == 2) ? pv[ji].z : pv[ji].w;
                    unsigned long long sp = splat2(p);
                    ffma2(O[ji][0], sp, vvp.a);
                    ffma2(O[ji][1], sp, vvp.b);
                }
            }
        }
    }

    #pragma unroll
    for (int ji = 0; ji < 4; ji++) {
        float rl = 1.0f / lrow[ji];
        float2 o0 = unpk(O[ji][0]), o1 = unpk(O[ji][1]);
        int row = t0 + ty * 4 + ji;
        float* dst = g_attn + ((size_t)row * BB + b) * EE + h * 64 + tx * 4;
        *(float4*)dst = make_float4(o0.x * rl, o0.y * rl, o1.x * rl, o1.y * rl);
    }
}

extern "C" void kernel_launch(void* const* d_in, const int* in_sizes, int n_in,
                              void* d_out, int out_size) {
    const float* query = (const float*)d_in[0];
    const float* ipw   = (const float*)d_in[1];
    const float* ipb   = (const float*)d_in[2];
    const float* fwd   = (const float*)d_in[3];
    const float* bwd   = (const float*)d_in[4];
    const float* hx    = (const float*)d_in[5];
    const float* cw    = (const float*)d_in[6];
    const float* ow    = (const float*)d_in[7];
    const float* ob    = (const float*)d_in[8];
    float* out = (float*)d_out;

    float *qkv_p, *ctx_p, *attn_p;
    __nv_bfloat16 *qh, *ql, *wh, *wl, *ah, *al, *oh, *ol;
    cudaGetSymbolAddress((void**)&qkv_p,  g_qkv);
    cudaGetSymbolAddress((void**)&ctx_p,  g_ctx);
    cudaGetSymbolAddress((void**)&attn_p, g_attn);
    cudaGetSymbolAddress((void**)&qh, g_qh);  cudaGetSymbolAddress((void**)&ql, g_ql);
    cudaGetSymbolAddress((void**)&wh, g_wh);  cudaGetSymbolAddress((void**)&wl, g_wl);
    cudaGetSymbolAddress((void**)&ah, g_ah);  cudaGetSymbolAddress((void**)&al, g_al);
    cudaGetSymbolAddress((void**)&oh, g_oh);  cudaGetSymbolAddress((void**)&ol, g_ol);

    const int gemm_smem = 2 * 65536;
    cudaFuncSetAttribute(hmma_gemm, cudaFuncAttributeMaxDynamicSharedMemorySize, gemm_smem);
    const int attn_smem = (4096 * 3 + 64 * 68 + 2049) * 4;
    cudaFuncSetAttribute(attn_kernel, cudaFuncAttributeMaxDynamicSharedMemorySize, attn_smem);

    // split inputs to bf16 hi/lo
    cvt_split<<<(MROWS * EE / 4 + 255) / 256, 256>>>((const float4*)query,
        (__nv_bfloat162*)qh, (__nv_bfloat162*)ql, MROWS * EE / 4);
    cvt_split<<<(QKVN * EE / 4 + 255) / 256, 256>>>((const float4*)ipw,
        (__nv_bfloat162*)wh, (__nv_bfloat162*)wl, QKVN * EE / 4);
    cvt_split<<<(EE * EE / 4 + 255) / 256, 256>>>((const float4*)ow,
        (__nv_bfloat162*)oh, (__nv_bfloat162*)ol, EE * EE / 4);

    // QKV projection (HMMA split-bf16)
    hmma_gemm<<<dim3(QKVN / 128, MROWS / 128), 256, gemm_smem>>>(qh, ql, wh, wl, ipb, qkv_p, QKVN, EE);

    // context gate GEMV
    ctx_kernel<<<MROWS / 8, 256>>>(query, cw, ctx_p);

    // fused flash attention
    attn_kernel<<<dim3(TT / 64, BB * HH), 256, attn_smem>>>(fwd, bwd, hx);

    // split attn output, then output projection (HMMA split-bf16)
    cvt_split<<<(MROWS * EE / 4 + 255) / 256, 256>>>((const float4*)attn_p,
        (__nv_bfloat162*)ah, (__nv_bfloat162*)al, MROWS * EE / 4);
    hmma_gemm<<<dim3(EE / 128, MROWS / 128), 256, gemm_smem>>>(ah, al, oh, ol, ob, out, EE, EE);
}

// round 5
// speedup vs baseline: 2.5978x; 1.6227x over previous
#include <cuda_runtime.h>
#include <cuda_bf16.h>
#include <cstdint>

#define TT    1024
#define BB    4
#define EE    1024
#define HH    16
#define ML    1024
#define MROWS (TT*BB)      // 4096
#define QKVN  (3*EE)       // 3072

// ---------------- scratch (device globals; allocation-free) ----------------
__device__ __nv_bfloat16 g_qkvh[MROWS * QKVN], g_qkvl[MROWS * QKVN]; // qkv hi/lo
__device__ float g_ctx[MROWS];
__device__ __nv_bfloat16 g_qh[MROWS * EE],  g_ql[MROWS * EE];     // query split
__device__ __nv_bfloat16 g_wh[QKVN * EE],   g_wl[QKVN * EE];      // in_proj_weight
__device__ __nv_bfloat16 g_ah[MROWS * EE],  g_al[MROWS * EE];     // attn out split
__device__ __nv_bfloat16 g_oh[EE * EE],     g_ol[EE * EE];        // out_w

// ---------------- PTX helpers (base-sm_103-safe) ----------------
__device__ __forceinline__ uint32_t smem_u32(const void* p) {
    uint32_t a;
    asm("{ .reg .u64 t; cvta.to.shared.u64 t, %1; cvt.u32.u64 %0, t; }" : "=r"(a) : "l"(p));
    return a;
}
__device__ __forceinline__ void cp_async16(uint32_t s, const void* g) {
    asm volatile("cp.async.cg.shared.global [%0], [%1], 16;" :: "r"(s), "l"(g));
}
__device__ __forceinline__ void cp_commit() { asm volatile("cp.async.commit_group;" ::: "memory"); }
template <int N> __device__ __forceinline__ void cp_wait() {
    asm volatile("cp.async.wait_group %0;" :: "n"(N) : "memory");
}
__device__ __forceinline__ void ldm_x4(uint32_t* r, uint32_t addr) {
    asm volatile("ldmatrix.sync.aligned.m8n8.x4.shared.b16 {%0,%1,%2,%3}, [%4];"
                 : "=r"(r[0]), "=r"(r[1]), "=r"(r[2]), "=r"(r[3]) : "r"(addr));
}
__device__ __forceinline__ void ldm_x4_t(uint32_t* r, uint32_t addr) {
    asm volatile("ldmatrix.sync.aligned.m8n8.x4.trans.shared.b16 {%0,%1,%2,%3}, [%4];"
                 : "=r"(r[0]), "=r"(r[1]), "=r"(r[2]), "=r"(r[3]) : "r"(addr));
}
__device__ __forceinline__ void mma_bf16(float* d, const uint32_t* a, const uint32_t* b) {
    asm volatile("mma.sync.aligned.m16n8k16.row.col.f32.bf16.bf16.f32 "
                 "{%0,%1,%2,%3}, {%4,%5,%6,%7}, {%8,%9}, {%0,%1,%2,%3};"
                 : "+f"(d[0]), "+f"(d[1]), "+f"(d[2]), "+f"(d[3])
                 : "r"(a[0]), "r"(a[1]), "r"(a[2]), "r"(a[3]), "r"(b[0]), "r"(b[1]));
}
__device__ __forceinline__ uint32_t pkbf(__nv_bfloat16 a, __nv_bfloat16 b) {
    __nv_bfloat162 t(a, b);
    return *(uint32_t*)&t;
}
// split a,b into bf16 hi/lo packed pairs
__device__ __forceinline__ void split2(float a, float b, uint32_t& h, uint32_t& l) {
    __nv_bfloat16 ha = __float2bfloat16_rn(a), hb = __float2bfloat16_rn(b);
    __nv_bfloat16 la = __float2bfloat16_rn(a - __bfloat162float(ha));
    __nv_bfloat16 lb = __float2bfloat16_rn(b - __bfloat162float(hb));
    h = pkbf(ha, hb);
    l = pkbf(la, lb);
}
__device__ __forceinline__ float sigm(float g) {
    return __fdividef(1.f, 1.f + __expf(-g));
}

// ---------------- fp32 -> bf16 hi/lo split ----------------
__global__ __launch_bounds__(256) void cvt_split(
    const float4* __restrict__ x, __nv_bfloat162* __restrict__ hi,
    __nv_bfloat162* __restrict__ lo, int n4)
{
    int i = blockIdx.x * 256 + threadIdx.x;
    if (i >= n4) return;
    float4 v = x[i];
    uint32_t h0, l0, h1, l1;
    split2(v.x, v.y, h0, l0);
    split2(v.z, v.w, h1, l1);
    ((uint32_t*)hi)[2*i] = h0; ((uint32_t*)hi)[2*i+1] = h1;
    ((uint32_t*)lo)[2*i] = l0; ((uint32_t*)lo)[2*i+1] = l1;
}

// ---------------- split-bf16 HMMA GEMM (NT): C = bias + A W^T ----------------
// BF16OUT=0: fp32 C.  BF16OUT=1: write hi/lo bf16 to Ch/Cl.
template<int BF16OUT>
__global__ __launch_bounds__(256) void hmma_gemm(
    const __nv_bfloat16* __restrict__ Ah, const __nv_bfloat16* __restrict__ Al,
    const __nv_bfloat16* __restrict__ Bh, const __nv_bfloat16* __restrict__ Bl,
    const float* __restrict__ bias, float* __restrict__ C,
    __nv_bfloat16* __restrict__ Ch, __nv_bfloat16* __restrict__ Cl, int N, int K)
{
    extern __shared__ char dsm[];   // 2 stages x 64KB
    const int tid = threadIdx.x;
    const int wid = tid >> 5, lane = tid & 31;
    const int n0 = blockIdx.x * 128, m0 = blockIdx.y * 128;
    const uint32_t sbase = smem_u32(dsm);

    const int mb = (wid >> 1) * 32;
    const int nb = (wid & 1) * 64;

    float acc[16][4];
    #pragma unroll
    for (int i = 0; i < 16; i++)
        #pragma unroll
        for (int j = 0; j < 4; j++) acc[i][j] = 0.f;

    const int nkt = K >> 6;

    auto load_tile = [&](int kt, int stage) {
        uint32_t sb = sbase + stage * 65536;
        const int koff = kt * 64;
        #pragma unroll
        for (int i = 0; i < 16; i++) {
            int c = tid + 256 * i;
            int sub = c >> 10;
            int idx = c & 1023;
            int row = idx >> 3, ch = idx & 7;
            const __nv_bfloat16* src =
                (sub == 0) ? Ah + (size_t)(m0 + row) * K :
                (sub == 1) ? Al + (size_t)(m0 + row) * K :
                (sub == 2) ? Bh + (size_t)(n0 + row) * K :
                             Bl + (size_t)(n0 + row) * K;
            uint32_t saddr = sb + sub * 16384 + row * 128 + ((ch ^ (row & 7)) << 4);
            cp_async16(saddr, src + koff + ch * 8);
        }
        cp_commit();
    };

    const int arow = lane & 15, ach = lane >> 4;
    const int brow = (lane & 7) + ((lane >> 4) << 3), bch = (lane >> 3) & 1;

    load_tile(0, 0);
    for (int kt = 0; kt < nkt; kt++) {
        const int s = kt & 1;
        cp_wait<0>();
        __syncthreads();
        if (kt + 1 < nkt) load_tile(kt + 1, s ^ 1);

        uint32_t sb = sbase + s * 65536;
        #pragma unroll
        for (int kc = 0; kc < 4; kc++) {
            uint32_t fa[2][2][4];
            uint32_t fb[2][4][4];
            #pragma unroll
            for (int mt = 0; mt < 2; mt++) {
                int row = mb + mt * 16 + arow;
                int ch = kc * 2 + ach;
                uint32_t off = row * 128 + ((ch ^ (row & 7)) << 4);
                ldm_x4(fa[0][mt], sb + off);
                ldm_x4(fa[1][mt], sb + 16384 + off);
            }
            #pragma unroll
            for (int bt = 0; bt < 4; bt++) {
                int row = nb + bt * 16 + brow;
                int ch = kc * 2 + bch;
                uint32_t off = row * 128 + ((ch ^ (row & 7)) << 4);
                ldm_x4(fb[0][bt], sb + 32768 + off);
                ldm_x4(fb[1][bt], sb + 49152 + off);
            }
            #pragma unroll
            for (int mt = 0; mt < 2; mt++)
                #pragma unroll
                for (int nt = 0; nt < 8; nt++) {
                    const uint32_t* bh = &fb[0][nt >> 1][(nt & 1) * 2];
                    const uint32_t* bl = &fb[1][nt >> 1][(nt & 1) * 2];
                    float* d = acc[mt * 8 + nt];
                    mma_bf16(d, fa[0][mt], bh);
                    mma_bf16(d, fa[0][mt], bl);
                    mma_bf16(d, fa[1][mt], bh);
                }
        }
        __syncthreads();
    }

    const int lr = lane >> 2, lc = (lane & 3) * 2;
    #pragma unroll
    for (int mt = 0; mt < 2; mt++)
        #pragma unroll
        for (int nt = 0; nt < 8; nt++) {
            int n = n0 + nb + nt * 8 + lc;
            float2 bv = *(const float2*)(bias + n);
            float* d = acc[mt * 8 + nt];
            int r0 = m0 + mb + mt * 16 + lr;
            float v0 = d[0] + bv.x, v1 = d[1] + bv.y;
            float v2 = d[2] + bv.x, v3 = d[3] + bv.y;
            if (BF16OUT) {
                uint32_t h01, l01, h23, l23;
                split2(v0, v1, h01, l01);
                split2(v2, v3, h23, l23);
                *(uint32_t*)(Ch + (size_t)r0 * N + n) = h01;
                *(uint32_t*)(Cl + (size_t)r0 * N + n) = l01;
                *(uint32_t*)(Ch + (size_t)(r0 + 8) * N + n) = h23;
                *(uint32_t*)(Cl + (size_t)(r0 + 8) * N + n) = l23;
            } else {
                *(float2*)(C + (size_t)r0 * N + n) = make_float2(v0, v1);
                *(float2*)(C + (size_t)(r0 + 8) * N + n) = make_float2(v2, v3);
            }
        }
}

// ---------------- ctx GEMV ----------------
__global__ __launch_bounds__(256) void ctx_kernel(
    const float* __restrict__ q, const float* __restrict__ w, float* __restrict__ out)
{
    int row = blockIdx.x * 8 + (threadIdx.x >> 5);
    int lane = threadIdx.x & 31;
    const float* qr = q + (size_t)row * EE;
    float s = 0.f;
    #pragma unroll
    for (int i = 0; i < EE; i += 128) {
        float4 qa = *(const float4*)(qr + i + lane * 4);
        float4 wa = *(const float4*)(w + i + lane * 4);
        s += qa.x * wa.x + qa.y * wa.y + qa.z * wa.z + qa.w * wa.w;
    }
    #pragma unroll
    for (int o = 16; o; o >>= 1) s += __shfl_xor_sync(0xffffffffu, s, o);
    if (!lane) out[row] = s;
}

// ---------------- HMMA flash attention with sigmoid-gate bias ----------------
// CTA: 64 q rows, 4 warps (m16 each). s chunks of 64, double-buffered cp.async.
// S = Qh*Kh + Qh*Kl + Ql*Kh; p = exp(S-m)*sigmoid(ctx+pos+hx); O via split-P HMMA.
// smem: stage0 @0 (Kh|Kl|Vh|Vl 8KB each), stage1 @32768, pos @65536 (2049 f32).
__global__ __launch_bounds__(128, 2) void attn_mma(
    const __nv_bfloat16* __restrict__ qkvh, const __nv_bfloat16* __restrict__ qkvl,
    const float* __restrict__ fwd, const float* __restrict__ bwd,
    const float* __restrict__ head_x, const float* __restrict__ ctx,
    __nv_bfloat16* __restrict__ outh, __nv_bfloat16* __restrict__ outl)
{
    extern __shared__ char dsm[];
    const int tid = threadIdx.x, w = tid >> 5, lane = tid & 31;
    const int t0 = blockIdx.x * 64;
    const int b = blockIdx.y >> 4, h = blockIdx.y & 15;
    const uint32_t sb0 = smem_u32(dsm);
    float* pos = (float*)(dsm + 65536);

    for (int j = tid; j < 2049; j += 128)
        pos[j] = (j < 1024) ? fwd[j] : ((j == 1024) ? 0.f : bwd[j - 1025]);

    // ---- stage Q (hi @0, lo @8192) and build Q fragments ----
    #pragma unroll
    for (int i = 0; i < 8; i++) {
        int c = tid + 128 * i;
        int arr = c >> 9;
        int idx = c & 511, row = idx >> 3, ch = idx & 7;
        const __nv_bfloat16* src = (arr ? qkvl : qkvh)
            + ((size_t)(t0 + row) * BB + b) * QKVN + h * 64 + ch * 8;
        cp_async16(sb0 + arr * 8192 + row * 128 + ((ch ^ (row & 7)) << 4), src);
    }
    cp_commit();
    cp_wait<0>();
    __syncthreads();

    uint32_t qfh[4][4], qfl[4][4];
    {
        int arow = w * 16 + (lane & 15);
        int ach = lane >> 4;
        #pragma unroll
        for (int kc = 0; kc < 4; kc++) {
            uint32_t off = arow * 128 + (((kc * 2 + ach) ^ (arow & 7)) << 4);
            ldm_x4(qfh[kc], sb0 + off);
            ldm_x4(qfl[kc], sb0 + 8192 + off);
        }
    }
    __syncthreads();   // Q read done; stage0 free for KV

    const float hxv = __ldg(head_x + h);
    const int myrow = t0 + w * 16 + (lane >> 2);
    float ct0 = g_ctx[(size_t)myrow * BB + b] + hxv;
    float ct1 = g_ctx[(size_t)(myrow + 8) * BB + b] + hxv;
    // (reads g_ctx directly; ctx arg kept for signature clarity)
    (void)ctx;

    float m0 = -1e30f, m1 = -1e30f, l0 = 0.f, l1 = 0.f;
    float O[8][4];
    #pragma unroll
    for (int i = 0; i < 8; i++)
        #pragma unroll
        for (int j = 0; j < 4; j++) O[i][j] = 0.f;

    auto load_kv = [&](int it, int stage) {
        uint32_t sb = sb0 + stage * 32768;
        int s0 = it * 64;
        #pragma unroll
        for (int i = 0; i < 16; i++) {
            int c = tid + 128 * i;        // 0..2047
            int sub = c >> 9;             // 0 Kh,1 Kl,2 Vh,3 Vl
            int idx = c & 511, row = idx >> 3, ch = idx & 7;
            size_t gb = ((size_t)(s0 + row) * BB + b) * QKVN + h * 64 + ch * 8;
            const __nv_bfloat16* src =
                (sub == 0) ? qkvh + gb + EE :
                (sub == 1) ? qkvl + gb + EE :
                (sub == 2) ? qkvh + gb + 2 * EE :
                             qkvl + gb + 2 * EE;
            cp_async16(sb + sub * 8192 + row * 128 + ((ch ^ (row & 7)) << 4), src);
        }
        cp_commit();
    };

    const int brow = (lane & 7) + ((lane >> 4) << 3), bch = (lane >> 3) & 1;
    const int vsrow = (lane & 7) + (((lane >> 3) & 1) << 3), vch = lane >> 4;

    load_kv(0, 0);
    for (int it = 0; it < 16; it++) {
        const int st = it & 1;
        cp_wait<0>();
        __syncthreads();
        if (it + 1 < 16) load_kv(it + 1, st ^ 1);
        const uint32_t kb = sb0 + st * 32768;
        const int s0 = it * 64;

        // ---- S = Q K^T ----
        float S[8][4];
        #pragma unroll
        for (int i = 0; i < 8; i++)
            #pragma unroll
            for (int j = 0; j < 4; j++) S[i][j] = 0.f;
        #pragma unroll
        for (int kc = 0; kc < 4; kc++) {
            uint32_t kh[4][4], kl[4][4];
            #pragma unroll
            for (int g = 0; g < 4; g++) {
                int row = g * 16 + brow;
                uint32_t off = row * 128 + (((kc * 2 + bch) ^ (row & 7)) << 4);
                ldm_x4(kh[g], kb + off);
                ldm_x4(kl[g], kb + 8192 + off);
            }
            #pragma unroll
            for (int nt = 0; nt < 8; nt++) {
                const uint32_t* bh = &kh[nt >> 1][(nt & 1) * 2];
                const uint32_t* bl = &kl[nt >> 1][(nt & 1) * 2];
                mma_bf16(S[nt], qfh[kc], bh);
                mma_bf16(S[nt], qfh[kc], bl);
                mma_bf16(S[nt], qfl[kc], bh);
            }
        }

        // ---- online softmax on raw-S max; p = exp(S-m)*sigmoid(gate) ----
        float mx0 = -1e30f, mx1 = -1e30f;
        #pragma unroll
        for (int nt = 0; nt < 8; nt++) {
            mx0 = fmaxf(mx0, fmaxf(S[nt][0], S[nt][1]));
            mx1 = fmaxf(mx1, fmaxf(S[nt][2], S[nt][3]));
        }
        #pragma unroll
        for (int o = 1; o <= 2; o <<= 1) {
            mx0 = fmaxf(mx0, __shfl_xor_sync(0xffffffffu, mx0, o));
            mx1 = fmaxf(mx1, __shfl_xor_sync(0xffffffffu, mx1, o));
        }
        float mn0 = fmaxf(m0, mx0), mn1 = fmaxf(m1, mx1);
        float sc0 = __expf(m0 - mn0), sc1 = __expf(m1 - mn1);
        m0 = mn0; m1 = mn1;

        float ls0 = 0.f, ls1 = 0.f;
        uint32_t Ph[8][2], Pl[8][2];
        const int dbase = s0 + (lane & 3) * 2 - myrow + ML;
        #pragma unroll
        for (int nt = 0; nt < 8; nt++) {
            int d0 = dbase + nt * 8;
            float p0 = __expf(S[nt][0] - m0) * sigm(ct0 + pos[d0]);
            float p1 = __expf(S[nt][1] - m0) * sigm(ct0 + pos[d0 + 1]);
            float p2 = __expf(S[nt][2] - m1) * sigm(ct1 + pos[d0 - 8]);
            float p3 = __expf(S[nt][3] - m1) * sigm(ct1 + pos[d0 - 7]);
            ls0 += p0 + p1; ls1 += p2 + p3;
            O[nt][0] *= sc0; O[nt][1] *= sc0; O[nt][2] *= sc1; O[nt][3] *= sc1;
            split2(p0, p1, Ph[nt][0], Pl[nt][0]);
            split2(p2, p3, Ph[nt][1], Pl[nt][1]);
        }
        #pragma unroll
        for (int o = 1; o <= 2; o <<= 1) {
            ls0 += __shfl_xor_sync(0xffffffffu, ls0, o);
            ls1 += __shfl_xor_sync(0xffffffffu, ls1, o);
        }
        l0 = l0 * sc0 + ls0;
        l1 = l1 * sc1 + ls1;

        // ---- O += P V  (V via ldmatrix.trans) ----
        #pragma unroll
        for (int j = 0; j < 4; j++) {
            uint32_t vh[4][4], vl[4][4];
            #pragma unroll
            for (int g = 0; g < 4; g++) {
                int row = j * 16 + vsrow;
                int ch = 2 * g + vch;
                uint32_t off = row * 128 + ((ch ^ (row & 7)) << 4);
                ldm_x4_t(vh[g], kb + 16384 + off);
                ldm_x4_t(vl[g], kb + 24576 + off);
            }
            uint32_t aph[4] = {Ph[2*j][0], Ph[2*j][1], Ph[2*j+1][0], Ph[2*j+1][1]};
            uint32_t apl[4] = {Pl[2*j][0], Pl[2*j][1], Pl[2*j+1][0], Pl[2*j+1][1]};
            #pragma unroll
            for (int nd = 0; nd < 8; nd++) {
                const uint32_t* bh = &vh[nd >> 1][(nd & 1) * 2];
                const uint32_t* bl = &vl[nd >> 1][(nd & 1) * 2];
                mma_bf16(O[nd], aph, bh);
                mma_bf16(O[nd], aph, bl);
                mma_bf16(O[nd], apl, bh);
            }
        }
    }

    // ---- finalize: O/l, split to bf16 hi/lo, write (t*B+b, E) ----
    float rl0 = __fdividef(1.f, l0), rl1 = __fdividef(1.f, l1);
    #pragma unroll
    for (int nt = 0; nt < 8; nt++) {
        int d = h * 64 + nt * 8 + (lane & 3) * 2;
        size_t r0 = ((size_t)myrow * BB + b) * EE + d;
        size_t r1 = ((size_t)(myrow + 8) * BB + b) * EE + d;
        uint32_t h01, l01, h23, l23;
        split2(O[nt][0] * rl0, O[nt][1] * rl0, h01, l01);
        split2(O[nt][2] * rl1, O[nt][3] * rl1, h23, l23);
        *(uint32_t*)(outh + r0) = h01; *(uint32_t*)(outl + r0) = l01;
        *(uint32_t*)(outh + r1) = h23; *(uint32_t*)(outl + r1) = l23;
    }
}

extern "C" void kernel_launch(void* const* d_in, const int* in_sizes, int n_in,
                              void* d_out, int out_size) {
    const float* query = (const float*)d_in[0];
    const float* ipw   = (const float*)d_in[1];
    const float* ipb   = (const float*)d_in[2];
    const float* fwd   = (const float*)d_in[3];
    const float* bwd   = (const float*)d_in[4];
    const float* hx    = (const float*)d_in[5];
    const float* cw    = (const float*)d_in[6];
    const float* ow    = (const float*)d_in[7];
    const float* ob    = (const float*)d_in[8];
    float* out = (float*)d_out;

    float *ctx_p;
    __nv_bfloat16 *qkvh, *qkvl, *qh, *ql, *wh, *wl, *ah, *al, *oh, *ol;
    cudaGetSymbolAddress((void**)&ctx_p, g_ctx);
    cudaGetSymbolAddress((void**)&qkvh, g_qkvh); cudaGetSymbolAddress((void**)&qkvl, g_qkvl);
    cudaGetSymbolAddress((void**)&qh, g_qh);  cudaGetSymbolAddress((void**)&ql, g_ql);
    cudaGetSymbolAddress((void**)&wh, g_wh);  cudaGetSymbolAddress((void**)&wl, g_wl);
    cudaGetSymbolAddress((void**)&ah, g_ah);  cudaGetSymbolAddress((void**)&al, g_al);
    cudaGetSymbolAddress((void**)&oh, g_oh);  cudaGetSymbolAddress((void**)&ol, g_ol);

    const int gemm_smem = 2 * 65536;
    cudaFuncSetAttribute(hmma_gemm<0>, cudaFuncAttributeMaxDynamicSharedMemorySize, gemm_smem);
    cudaFuncSetAttribute(hmma_gemm<1>, cudaFuncAttributeMaxDynamicSharedMemorySize, gemm_smem);
    const int attn_smem = 65536 + 2052 * 4;
    cudaFuncSetAttribute(attn_mma, cudaFuncAttributeMaxDynamicSharedMemorySize, attn_smem);

    // split inputs to bf16 hi/lo
    cvt_split<<<(MROWS * EE / 4 + 255) / 256, 256>>>((const float4*)query,
        (__nv_bfloat162*)qh, (__nv_bfloat162*)ql, MROWS * EE / 4);
    cvt_split<<<(QKVN * EE / 4 + 255) / 256, 256>>>((const float4*)ipw,
        (__nv_bfloat162*)wh, (__nv_bfloat162*)wl, QKVN * EE / 4);
    cvt_split<<<(EE * EE / 4 + 255) / 256, 256>>>((const float4*)ow,
        (__nv_bfloat162*)oh, (__nv_bfloat162*)ol, EE * EE / 4);

    // QKV projection -> hi/lo bf16 directly
    hmma_gemm<1><<<dim3(QKVN / 128, MROWS / 128), 256, gemm_smem>>>(
        qh, ql, wh, wl, ipb, nullptr, qkvh, qkvl, QKVN, EE);

    // context gate GEMV
    ctx_kernel<<<MROWS / 8, 256>>>(query, cw, ctx_p);

    // fused HMMA flash attention -> hi/lo bf16
    attn_mma<<<dim3(TT / 64, BB * HH), 128, attn_smem>>>(
        qkvh, qkvl, fwd, bwd, hx, ctx_p, ah, al);

    // output projection -> fp32 d_out
    hmma_gemm<0><<<dim3(EE / 128, MROWS / 128), 256, gemm_smem>>>(
        ah, al, oh, ol, ob, out, nullptr, nullptr, EE, EE);
}